// round 1
// baseline (speedup 1.0000x reference)
#include <cuda_runtime.h>
#include <math.h>

#define NTOK 4096
#define EDIM 1024
#define NH   16
#define HD   32
#define NL   6

// ---------------- scratch (device globals; no allocs allowed) ----------------
__device__ float g_z  [NTOK * EDIM];        // 16 MB
__device__ float g_tmp[NTOK * EDIM];        // 16 MB
__device__ float g_an [NTOK * EDIM];        // 16 MB
__device__ float g_q  [NH * NTOK * HD];     // 8 MB
__device__ float g_k  [NH * NTOK * HD];     // 8 MB
__device__ float g_v  [NH * NTOK * HD];     // 8 MB
__device__ float g_o  [NTOK * NH * HD];     // 8 MB   layout [n][h*32+v]
__device__ float g_ff [NTOK * 2 * EDIM];    // 32 MB

// ---------------- embedding: z = table[ctx] + pos ----------------
__global__ void embed_kernel(const int* __restrict__ ctx,
                             const float* __restrict__ table,
                             const float* __restrict__ pos) {
    int n = blockIdx.x;
    int tok = ctx[n];
    const float4* tb = (const float4*)(table + (size_t)tok * EDIM);
    const float4* pp = (const float4*)(pos + (size_t)n * EDIM);
    float4* zz = (float4*)(g_z + (size_t)n * EDIM);
    int i = threadIdx.x;                      // 256 threads, E/4 = 256 float4
    float4 a = tb[i], b = pp[i];
    zz[i] = make_float4(a.x + b.x, a.y + b.y, a.z + b.z, a.w + b.w);
}

// ---------------- per-head projection: out[h][n][v] = A[n,:] @ W[h][:,v] ----------------
// grid (NTOK/64, NH), block 256. W layout [H][E][V].
__global__ __launch_bounds__(256)
void head_gemm_kernel(const float* __restrict__ A,
                      const float* __restrict__ W,
                      float* __restrict__ out) {
    __shared__ float As[64][64];
    __shared__ float Bs[64][32];
    int h = blockIdx.y;
    int row0 = blockIdx.x * 64;
    const float* Wh = W + (size_t)h * EDIM * HD;
    int t = threadIdx.x;
    int tcol = t & 31;
    int trow0 = (t >> 5) * 8;
    float acc[8] = {0.f, 0.f, 0.f, 0.f, 0.f, 0.f, 0.f, 0.f};

    for (int k0 = 0; k0 < EDIM; k0 += 64) {
        #pragma unroll
        for (int j = 0; j < 4; j++) {         // A tile 64x64 = 1024 float4
            int idx = t + j * 256;
            int r = idx >> 4, c4 = idx & 15;
            *(float4*)&As[r][c4 * 4] =
                *(const float4*)&A[(size_t)(row0 + r) * EDIM + k0 + c4 * 4];
        }
        #pragma unroll
        for (int j = 0; j < 2; j++) {         // W tile 64x32 = 512 float4
            int idx = t + j * 256;
            int r = idx >> 3, c4 = idx & 7;
            *(float4*)&Bs[r][c4 * 4] =
                *(const float4*)&Wh[(size_t)(k0 + r) * HD + c4 * 4];
        }
        __syncthreads();
        #pragma unroll 16
        for (int kk = 0; kk < 64; kk++) {
            float b = Bs[kk][tcol];
            #pragma unroll
            for (int i = 0; i < 8; i++)
                acc[i] += As[trow0 + i][kk] * b;
        }
        __syncthreads();
    }
    #pragma unroll
    for (int i = 0; i < 8; i++)
        out[(size_t)h * NTOK * HD + (size_t)(row0 + trow0 + i) * HD + tcol] = acc[i];
}

// ---------------- flash attention (d=32, full softmax) ----------------
// grid (NTOK/128, NH), block 128. One query row per thread.
__global__ __launch_bounds__(128)
void attn_kernel() {
    __shared__ float Ks[32][32];
    __shared__ float Vs[32][32];
    int h = blockIdx.y;
    int qrow = blockIdx.x * 128 + threadIdx.x;
    const float scale = 0.17677669529663687f;   // 1/sqrt(32)

    float q[32], o[32];
    const float* qp = g_q + (size_t)h * NTOK * HD + (size_t)qrow * HD;
    #pragma unroll
    for (int v4 = 0; v4 < 8; v4++) {
        float4 t4 = *(const float4*)&qp[v4 * 4];
        q[v4 * 4 + 0] = t4.x * scale; q[v4 * 4 + 1] = t4.y * scale;
        q[v4 * 4 + 2] = t4.z * scale; q[v4 * 4 + 3] = t4.w * scale;
    }
    #pragma unroll
    for (int v = 0; v < 32; v++) o[v] = 0.f;
    float m = -1e30f, l = 0.f;

    const float* kbase = g_k + (size_t)h * NTOK * HD;
    const float* vbase = g_v + (size_t)h * NTOK * HD;
    int t = threadIdx.x;

    for (int kb = 0; kb < NTOK; kb += 32) {
        #pragma unroll
        for (int j = 0; j < 2; j++) {         // 256 float4 per tile, 128 threads
            int idx = t + j * 128;
            int r = idx >> 3, c4 = idx & 7;
            *(float4*)&Ks[r][c4 * 4] = *(const float4*)&kbase[(size_t)(kb + r) * HD + c4 * 4];
            *(float4*)&Vs[r][c4 * 4] = *(const float4*)&vbase[(size_t)(kb + r) * HD + c4 * 4];
        }
        __syncthreads();

        float s[32];
        float mloc = -1e30f;
        #pragma unroll
        for (int j = 0; j < 32; j++) {
            float acc = 0.f;
            #pragma unroll
            for (int v4 = 0; v4 < 8; v4++) {
                float4 kk = *(float4*)&Ks[j][v4 * 4];
                acc += q[v4 * 4 + 0] * kk.x + q[v4 * 4 + 1] * kk.y
                     + q[v4 * 4 + 2] * kk.z + q[v4 * 4 + 3] * kk.w;
            }
            s[j] = acc;
            mloc = fmaxf(mloc, acc);
        }
        float mnew = fmaxf(m, mloc);
        float alpha = __expf(m - mnew);
        float psum = 0.f;
        #pragma unroll
        for (int j = 0; j < 32; j++) {
            s[j] = __expf(s[j] - mnew);
            psum += s[j];
        }
        l = l * alpha + psum;
        #pragma unroll
        for (int v = 0; v < 32; v++) o[v] *= alpha;
        #pragma unroll
        for (int j = 0; j < 32; j++) {
            float p = s[j];
            #pragma unroll
            for (int v4 = 0; v4 < 8; v4++) {
                float4 vv = *(float4*)&Vs[j][v4 * 4];
                o[v4 * 4 + 0] += p * vv.x; o[v4 * 4 + 1] += p * vv.y;
                o[v4 * 4 + 2] += p * vv.z; o[v4 * 4 + 3] += p * vv.w;
            }
        }
        m = mnew;
        __syncthreads();
    }

    float inv = 1.f / l;
    float* op = g_o + (size_t)qrow * (NH * HD) + (size_t)h * HD;
    #pragma unroll
    for (int v4 = 0; v4 < 8; v4++) {
        float4 w;
        w.x = o[v4 * 4 + 0] * inv; w.y = o[v4 * 4 + 1] * inv;
        w.z = o[v4 * 4 + 2] * inv; w.w = o[v4 * 4 + 3] * inv;
        *(float4*)&op[v4 * 4] = w;
    }
}

// ---------------- generic tiled SGEMM: C = A@B (+bias) (+leaky) (+res) ----------------
// BM=BN=64, BK=16, 256 threads, 4x4 microtile. A [M,K] rm, B [K,N] rm.
template<int DO_BIAS, int DO_LEAKY, int DO_RES>
__global__ __launch_bounds__(256)
void sgemm_kernel(const float* __restrict__ A, const float* __restrict__ B,
                  const float* __restrict__ bias, const float* __restrict__ res,
                  float* __restrict__ C, int M, int N, int K) {
    __shared__ float As[16][64];
    __shared__ float Bs[16][64];
    int bx = blockIdx.x * 64, by = blockIdx.y * 64;
    int t = threadIdx.x;
    int tx = t & 15, ty = t >> 4;
    float acc[4][4] = {};

    for (int k0 = 0; k0 < K; k0 += 16) {
        {   // A tile 64x16 -> transposed As[k][m]
            int r = t >> 2, qd = t & 3;
            float4 av = *(const float4*)&A[(size_t)(by + r) * K + k0 + qd * 4];
            As[qd * 4 + 0][r] = av.x; As[qd * 4 + 1][r] = av.y;
            As[qd * 4 + 2][r] = av.z; As[qd * 4 + 3][r] = av.w;
        }
        {   // B tile 16x64
            int r = t >> 4, c4 = t & 15;
            *(float4*)&Bs[r][c4 * 4] = *(const float4*)&B[(size_t)(k0 + r) * N + bx + c4 * 4];
        }
        __syncthreads();
        #pragma unroll
        for (int k = 0; k < 16; k++) {
            float4 a = *(float4*)&As[k][ty * 4];
            float4 b = *(float4*)&Bs[k][tx * 4];
            float aa[4] = {a.x, a.y, a.z, a.w};
            float bb[4] = {b.x, b.y, b.z, b.w};
            #pragma unroll
            for (int i = 0; i < 4; i++)
                #pragma unroll
                for (int j = 0; j < 4; j++)
                    acc[i][j] += aa[i] * bb[j];
        }
        __syncthreads();
    }
    #pragma unroll
    for (int i = 0; i < 4; i++) {
        int row = by + ty * 4 + i;
        #pragma unroll
        for (int j = 0; j < 4; j++) {
            int col = bx + tx * 4 + j;
            float c = acc[i][j];
            if (DO_BIAS)  c += bias[col];
            if (DO_LEAKY) c = (c > 0.f) ? c : 0.01f * c;
            if (DO_RES)   c += res[(size_t)row * N + col];
            C[(size_t)row * N + col] = c;
        }
    }
}

// ---------------- row LayerNorm (ddof=1, no eps), E=1024, 256 threads ----------------
__global__ __launch_bounds__(256)
void ln_kernel(const float* __restrict__ in, float* __restrict__ out) {
    int n = blockIdx.x;
    const float* x = in + (size_t)n * EDIM;
    float xv[4];
    float s1 = 0.f, s2 = 0.f;
    #pragma unroll
    for (int i = 0; i < 4; i++) {
        float v = x[threadIdx.x + i * 256];
        xv[i] = v; s1 += v; s2 += v * v;
    }
    #pragma unroll
    for (int off = 16; off; off >>= 1) {
        s1 += __shfl_down_sync(0xffffffffu, s1, off);
        s2 += __shfl_down_sync(0xffffffffu, s2, off);
    }
    __shared__ float r1[8], r2[8];
    __shared__ float mean_s, inv_s;
    int w = threadIdx.x >> 5;
    if ((threadIdx.x & 31) == 0) { r1[w] = s1; r2[w] = s2; }
    __syncthreads();
    if (threadIdx.x == 0) {
        float a = 0.f, b = 0.f;
        #pragma unroll
        for (int i = 0; i < 8; i++) { a += r1[i]; b += r2[i]; }
        float mean = a / (float)EDIM;
        float var = (b - (float)EDIM * mean * mean) / (float)(EDIM - 1);
        mean_s = mean;
        inv_s = rsqrtf(var);
    }
    __syncthreads();
    float mean = mean_s, inv = inv_s;
    #pragma unroll
    for (int i = 0; i < 4; i++)
        out[(size_t)n * EDIM + threadIdx.x + i * 256] = (xv[i] - mean) * inv;
}

// ---------------- host orchestration ----------------
extern "C" void kernel_launch(void* const* d_in, const int* in_sizes, int n_in,
                              void* d_out, int out_size) {
    const int*   ctx   = (const int*)  d_in[0];
    const float* table = (const float*)d_in[1];
    const float* pos   = (const float*)d_in[2];
    const float* Wq    = (const float*)d_in[3];
    const float* Wk    = (const float*)d_in[4];
    const float* Wv    = (const float*)d_in[5];
    const float* Wo    = (const float*)d_in[6];
    const float* W1    = (const float*)d_in[7];
    const float* b1    = (const float*)d_in[8];
    const float* W2    = (const float*)d_in[9];
    const float* b2    = (const float*)d_in[10];

    float *z, *tmp, *an, *q, *k, *v, *o, *ff;
    cudaGetSymbolAddress((void**)&z,   g_z);
    cudaGetSymbolAddress((void**)&tmp, g_tmp);
    cudaGetSymbolAddress((void**)&an,  g_an);
    cudaGetSymbolAddress((void**)&q,   g_q);
    cudaGetSymbolAddress((void**)&k,   g_k);
    cudaGetSymbolAddress((void**)&v,   g_v);
    cudaGetSymbolAddress((void**)&o,   g_o);
    cudaGetSymbolAddress((void**)&ff,  g_ff);

    embed_kernel<<<NTOK, 256>>>(ctx, table, pos);

    const size_t wqkv_stride = (size_t)NH * EDIM * HD;   // 524288
    const size_t wo_stride   = (size_t)NH * HD * EDIM;   // 524288
    const size_t w1_stride   = (size_t)EDIM * 2 * EDIM;
    const size_t w2_stride   = (size_t)2 * EDIM * EDIM;

    for (int l = 0; l < NL; l++) {
        const float* wq = Wq + (size_t)l * wqkv_stride;
        const float* wk = Wk + (size_t)l * wqkv_stride;
        const float* wv = Wv + (size_t)l * wqkv_stride;
        const float* wo = Wo + (size_t)l * wo_stride;
        const float* w1 = W1 + (size_t)l * w1_stride;
        const float* bb1 = b1 + (size_t)l * 2 * EDIM;
        const float* w2 = W2 + (size_t)l * w2_stride;
        const float* bb2 = b2 + (size_t)l * EDIM;

        dim3 gq(NTOK / 64, NH);
        head_gemm_kernel<<<gq, 256>>>(z, wq, q);
        head_gemm_kernel<<<gq, 256>>>(z, wk, k);
        head_gemm_kernel<<<gq, 256>>>(z, wv, v);

        attn_kernel<<<dim3(NTOK / 128, NH), 128>>>();

        // tmp = z + o @ Wo ; an = LN(tmp)
        sgemm_kernel<0, 0, 1><<<dim3(EDIM / 64, NTOK / 64), 256>>>(
            o, wo, nullptr, z, tmp, NTOK, EDIM, NH * HD);
        ln_kernel<<<NTOK, 256>>>(tmp, an);

        // ff = leaky(an @ W1 + b1)
        sgemm_kernel<1, 1, 0><<<dim3(2 * EDIM / 64, NTOK / 64), 256>>>(
            an, w1, bb1, nullptr, ff, NTOK, 2 * EDIM, EDIM);

        // tmp = an + ff @ W2 + b2 ; z = LN(tmp)  (last layer -> d_out)
        sgemm_kernel<1, 0, 1><<<dim3(EDIM / 64, NTOK / 64), 256>>>(
            ff, w2, bb2, an, tmp, NTOK, EDIM, 2 * EDIM);
        ln_kernel<<<NTOK, 256>>>(tmp, (l == NL - 1) ? (float*)d_out : z);
    }
}

// round 5
// speedup vs baseline: 1.2006x; 1.2006x over previous
#include <cuda_runtime.h>
#include <cuda_bf16.h>
#include <math.h>

#define NTOK 4096
#define EDIM 1024
#define NH   16
#define HD   32
#define NL   6

// ---------------- scratch (device globals; no allocs allowed) ----------------
__device__ float g_z  [NTOK * EDIM];           // 16 MB
__device__ float g_tmp[NTOK * EDIM];           // 16 MB
__device__ float g_an [NTOK * EDIM];           // 16 MB
__device__ float g_qkv[NTOK * 3 * EDIM / 2];   // [n][1536]: q | k | v, 25 MB
__device__ float g_o  [NTOK * NH * HD];        // 8 MB   layout [n][h*32+v]
__device__ float g_ff [NTOK * 2 * EDIM];       // 32 MB
__device__ float g_wt [NL * EDIM * 1536];      // 37.7 MB transposed QKV weights

// ---------------- embedding: z = table[ctx] + pos ----------------
__global__ void embed_kernel(const int* __restrict__ ctx,
                             const float* __restrict__ table,
                             const float* __restrict__ pos) {
    int n = blockIdx.x;
    int tok = ctx[n];
    const float4* tb = (const float4*)(table + (size_t)tok * EDIM);
    const float4* pp = (const float4*)(pos + (size_t)n * EDIM);
    float4* zz = (float4*)(g_z + (size_t)n * EDIM);
    int i = threadIdx.x;
    float4 a = tb[i], b = pp[i];
    zz[i] = make_float4(a.x + b.x, a.y + b.y, a.z + b.z, a.w + b.w);
}

// ---------------- weight transpose: g_wt[l][e][c], c = sel*512 + h*32 + v ----------------
__global__ void wt_kernel(const float* __restrict__ Wq,
                          const float* __restrict__ Wk,
                          const float* __restrict__ Wv) {
    int e = blockIdx.x;
    int l = blockIdx.y;
    #pragma unroll
    for (int i = 0; i < 6; i++) {
        int c = threadIdx.x + i * 256;          // 0..1535
        int sel = c >> 9;                        // /512
        int hv  = c & 511;
        const float* W = (sel == 0) ? Wq : (sel == 1) ? Wk : Wv;
        g_wt[((size_t)l * EDIM + e) * 1536 + c] =
            W[(size_t)l * 524288 + (size_t)(hv >> 5) * 32768 + (size_t)e * 32 + (hv & 31)];
    }
}

// ---------------- bf16x3 split mma GEMM ----------------
// C[M,N] = A[M,K] @ B[K,N] with fp32-class accuracy via 3x bf16 mma.
// BM=BN=128, BK=16, 256 threads (8 warps: 4 in M x 2 in N), warp tile 32x64.
__device__ __forceinline__ unsigned pack_bf16(__nv_bfloat16 lo, __nv_bfloat16 hi) {
    return (unsigned)__bfloat16_as_ushort(lo) | ((unsigned)__bfloat16_as_ushort(hi) << 16);
}

__device__ __forceinline__ void mma_bf16(float* d, const unsigned* a, unsigned b0, unsigned b1) {
    asm volatile(
        "mma.sync.aligned.m16n8k16.row.col.f32.bf16.bf16.f32 "
        "{%0,%1,%2,%3},{%4,%5,%6,%7},{%8,%9},{%0,%1,%2,%3};"
        : "+f"(d[0]), "+f"(d[1]), "+f"(d[2]), "+f"(d[3])
        : "r"(a[0]), "r"(a[1]), "r"(a[2]), "r"(a[3]), "r"(b0), "r"(b1));
}

// EPI: 0 none, 1 bias+leaky, 2 bias+res, 3 res
template<int EPI>
__global__ __launch_bounds__(256)
void gemm_kernel(const float* __restrict__ A, const float* __restrict__ B,
                 const float* __restrict__ bias, const float* __restrict__ res,
                 float* __restrict__ C,
                 int M, int N, int K, int lda, int ldb, int ldc) {
    // smem: [buf][comp(hi/mid)][row 128][kpair word 0..7, padded to 12]
    __shared__ unsigned As[2][2][128][12];
    __shared__ unsigned Bs[2][2][128][12];   // row here = n column, word = kpair

    const int t = threadIdx.x;
    const int lane = t & 31;
    const int wid = t >> 5;
    const int g = lane >> 2;      // 0..7
    const int q = lane & 3;       // 0..3
    const int warp_m = wid & 3;   // 4 warps along M
    const int warp_n = wid >> 2;  // 2 warps along N
    const int m0 = warp_m * 32;
    const int n0 = warp_n * 64;
    const int by = blockIdx.y * 128;
    const int bx = blockIdx.x * 128;

    // global load slots
    const int arow = t >> 2;       // 0..63 (and +64)
    const int akq  = t & 3;        // k-quad 0..3
    const int bkr  = t >> 5;       // 0..7 (and +8)
    const int bnq  = t & 31;       // 0..31

    float4 ra0, ra1, rb0, rb1;
    float acc[2][8][4];
    #pragma unroll
    for (int i = 0; i < 2; i++)
        #pragma unroll
        for (int j = 0; j < 8; j++)
            #pragma unroll
            for (int c = 0; c < 4; c++) acc[i][j][c] = 0.f;

    const int KT = K >> 4;

    auto load_regs = [&](int kt) {
        int k0 = kt << 4;
        ra0 = *(const float4*)(A + (size_t)(by + arow) * lda + k0 + akq * 4);
        ra1 = *(const float4*)(A + (size_t)(by + arow + 64) * lda + k0 + akq * 4);
        rb0 = *(const float4*)(B + (size_t)(k0 + bkr) * ldb + bx + bnq * 4);
        rb1 = *(const float4*)(B + (size_t)(k0 + bkr + 8) * ldb + bx + bnq * 4);
    };

    auto store_smem = [&](int buf) {
        // A: rows arow, arow+64; k = akq*4 .. +3  -> words akq*2, akq*2+1
        float av[2][4] = {{ra0.x, ra0.y, ra0.z, ra0.w}, {ra1.x, ra1.y, ra1.z, ra1.w}};
        #pragma unroll
        for (int half = 0; half < 2; half++) {
            int r = arow + half * 64;
            __nv_bfloat16 h[4], m[4];
            #pragma unroll
            for (int j = 0; j < 4; j++) {
                float x = av[half][j];
                h[j] = __float2bfloat16_rn(x);
                m[j] = __float2bfloat16_rn(x - __bfloat162float(h[j]));
            }
            As[buf][0][r][akq * 2 + 0] = pack_bf16(h[0], h[1]);
            As[buf][0][r][akq * 2 + 1] = pack_bf16(h[2], h[3]);
            As[buf][1][r][akq * 2 + 0] = pack_bf16(m[0], m[1]);
            As[buf][1][r][akq * 2 + 1] = pack_bf16(m[2], m[3]);
        }
        // B: k rows bkr, bkr+8; n = bnq*4 .. +3  (transpose to [n][k])
        float bv[2][4] = {{rb0.x, rb0.y, rb0.z, rb0.w}, {rb1.x, rb1.y, rb1.z, rb1.w}};
        unsigned short* bh = (unsigned short*)Bs[buf][0];
        unsigned short* bm = (unsigned short*)Bs[buf][1];
        #pragma unroll
        for (int half = 0; half < 2; half++) {
            int kr = bkr + half * 8;
            #pragma unroll
            for (int j = 0; j < 4; j++) {
                float x = bv[half][j];
                __nv_bfloat16 h = __float2bfloat16_rn(x);
                __nv_bfloat16 m = __float2bfloat16_rn(x - __bfloat162float(h));
                int n = bnq * 4 + j;
                bh[n * 24 + kr] = __bfloat16_as_ushort(h);
                bm[n * 24 + kr] = __bfloat16_as_ushort(m);
            }
        }
    };

    auto compute = [&](int buf) {
        unsigned a[2][2][4];   // [comp][mt][reg]
        #pragma unroll
        for (int comp = 0; comp < 2; comp++)
            #pragma unroll
            for (int mt = 0; mt < 2; mt++) {
                int r = m0 + mt * 16 + g;
                a[comp][mt][0] = As[buf][comp][r][q];
                a[comp][mt][1] = As[buf][comp][r + 8][q];
                a[comp][mt][2] = As[buf][comp][r][q + 4];
                a[comp][mt][3] = As[buf][comp][r + 8][q + 4];
            }
        #pragma unroll
        for (int nt = 0; nt < 8; nt++) {
            int n = n0 + nt * 8 + g;
            unsigned bh0 = Bs[buf][0][n][q], bh1 = Bs[buf][0][n][q + 4];
            unsigned bm0 = Bs[buf][1][n][q], bm1 = Bs[buf][1][n][q + 4];
            #pragma unroll
            for (int mt = 0; mt < 2; mt++) {
                mma_bf16(acc[mt][nt], a[0][mt], bh0, bh1);   // Ah*Bh
                mma_bf16(acc[mt][nt], a[0][mt], bm0, bm1);   // Ah*Bm
                mma_bf16(acc[mt][nt], a[1][mt], bh0, bh1);   // Am*Bh
            }
        }
    };

    load_regs(0);
    store_smem(0);
    __syncthreads();
    for (int kt = 0; kt < KT; kt++) {
        if (kt + 1 < KT) load_regs(kt + 1);
        compute(kt & 1);
        if (kt + 1 < KT) {
            __syncthreads();
            store_smem((kt + 1) & 1);
            __syncthreads();
        }
    }

    // epilogue
    #pragma unroll
    for (int mt = 0; mt < 2; mt++) {
        #pragma unroll
        for (int rr = 0; rr < 2; rr++) {           // c0/c1 then c2/c3 (row +8)
            int row = by + m0 + mt * 16 + g + rr * 8;
            #pragma unroll
            for (int nt = 0; nt < 8; nt++) {
                int col = bx + n0 + nt * 8 + q * 2;
                float v0 = acc[mt][nt][rr * 2 + 0];
                float v1 = acc[mt][nt][rr * 2 + 1];
                if (EPI == 1 || EPI == 2) {
                    float2 bb = *(const float2*)&bias[col];
                    v0 += bb.x; v1 += bb.y;
                }
                if (EPI == 1) {
                    v0 = (v0 > 0.f) ? v0 : 0.01f * v0;
                    v1 = (v1 > 0.f) ? v1 : 0.01f * v1;
                }
                if (EPI == 2 || EPI == 3) {
                    float2 rv = *(const float2*)&res[(size_t)row * ldc + col];
                    v0 += rv.x; v1 += rv.y;
                }
                *(float2*)&C[(size_t)row * ldc + col] = make_float2(v0, v1);
            }
        }
    }
}

// ---------------- flash attention (d=32, full softmax), SIMT fp32 ----------------
// grid (NTOK/128, NH), block 128. One query row per thread. Reads g_qkv [n][1536].
__global__ __launch_bounds__(128)
void attn_kernel() {
    __shared__ float Ks[32][32];
    __shared__ float Vs[32][32];
    int h = blockIdx.y;
    int qrow = blockIdx.x * 128 + threadIdx.x;
    const float scale = 0.17677669529663687f;   // 1/sqrt(32)

    float q[32], o[32];
    const float* qp = g_qkv + (size_t)qrow * 1536 + h * 32;
    #pragma unroll
    for (int v4 = 0; v4 < 8; v4++) {
        float4 t4 = *(const float4*)&qp[v4 * 4];
        q[v4 * 4 + 0] = t4.x * scale; q[v4 * 4 + 1] = t4.y * scale;
        q[v4 * 4 + 2] = t4.z * scale; q[v4 * 4 + 3] = t4.w * scale;
    }
    #pragma unroll
    for (int v = 0; v < 32; v++) o[v] = 0.f;
    float m = -1e30f, l = 0.f;

    const float* kbase = g_qkv + 512 + h * 32;
    const float* vbase = g_qkv + 1024 + h * 32;
    int t = threadIdx.x;

    for (int kb = 0; kb < NTOK; kb += 32) {
        #pragma unroll
        for (int j = 0; j < 2; j++) {
            int idx = t + j * 128;
            int r = idx >> 3, c4 = idx & 7;
            *(float4*)&Ks[r][c4 * 4] = *(const float4*)&kbase[(size_t)(kb + r) * 1536 + c4 * 4];
            *(float4*)&Vs[r][c4 * 4] = *(const float4*)&vbase[(size_t)(kb + r) * 1536 + c4 * 4];
        }
        __syncthreads();

        float s[32];
        float mloc = -1e30f;
        #pragma unroll
        for (int j = 0; j < 32; j++) {
            float acc = 0.f;
            #pragma unroll
            for (int v4 = 0; v4 < 8; v4++) {
                float4 kk = *(float4*)&Ks[j][v4 * 4];
                acc += q[v4 * 4 + 0] * kk.x + q[v4 * 4 + 1] * kk.y
                     + q[v4 * 4 + 2] * kk.z + q[v4 * 4 + 3] * kk.w;
            }
            s[j] = acc;
            mloc = fmaxf(mloc, acc);
        }
        float mnew = fmaxf(m, mloc);
        float alpha = __expf(m - mnew);
        float psum = 0.f;
        #pragma unroll
        for (int j = 0; j < 32; j++) {
            s[j] = __expf(s[j] - mnew);
            psum += s[j];
        }
        l = l * alpha + psum;
        #pragma unroll
        for (int v = 0; v < 32; v++) o[v] *= alpha;
        #pragma unroll
        for (int j = 0; j < 32; j++) {
            float p = s[j];
            #pragma unroll
            for (int v4 = 0; v4 < 8; v4++) {
                float4 vv = *(float4*)&Vs[j][v4 * 4];
                o[v4 * 4 + 0] += p * vv.x; o[v4 * 4 + 1] += p * vv.y;
                o[v4 * 4 + 2] += p * vv.z; o[v4 * 4 + 3] += p * vv.w;
            }
        }
        m = mnew;
        __syncthreads();
    }

    float inv = 1.f / l;
    float* op = g_o + (size_t)qrow * (NH * HD) + (size_t)h * HD;
    #pragma unroll
    for (int v4 = 0; v4 < 8; v4++) {
        float4 w;
        w.x = o[v4 * 4 + 0] * inv; w.y = o[v4 * 4 + 1] * inv;
        w.z = o[v4 * 4 + 2] * inv; w.w = o[v4 * 4 + 3] * inv;
        *(float4*)&op[v4 * 4] = w;
    }
}

// ---------------- row LayerNorm (ddof=1, no eps), E=1024, 256 threads ----------------
__global__ __launch_bounds__(256)
void ln_kernel(const float* __restrict__ in, float* __restrict__ out) {
    int n = blockIdx.x;
    const float* x = in + (size_t)n * EDIM;
    float xv[4];
    float s1 = 0.f, s2 = 0.f;
    #pragma unroll
    for (int i = 0; i < 4; i++) {
        float v = x[threadIdx.x + i * 256];
        xv[i] = v; s1 += v; s2 += v * v;
    }
    #pragma unroll
    for (int off = 16; off; off >>= 1) {
        s1 += __shfl_down_sync(0xffffffffu, s1, off);
        s2 += __shfl_down_sync(0xffffffffu, s2, off);
    }
    __shared__ float r1[8], r2[8];
    __shared__ float mean_s, inv_s;
    int w = threadIdx.x >> 5;
    if ((threadIdx.x & 31) == 0) { r1[w] = s1; r2[w] = s2; }
    __syncthreads();
    if (threadIdx.x == 0) {
        float a = 0.f, b = 0.f;
        #pragma unroll
        for (int i = 0; i < 8; i++) { a += r1[i]; b += r2[i]; }
        float mean = a / (float)EDIM;
        float var = (b - (float)EDIM * mean * mean) / (float)(EDIM - 1);
        mean_s = mean;
        inv_s = rsqrtf(var);
    }
    __syncthreads();
    float mean = mean_s, inv = inv_s;
    #pragma unroll
    for (int i = 0; i < 4; i++)
        out[(size_t)n * EDIM + threadIdx.x + i * 256] = (xv[i] - mean) * inv;
}

// ---------------- host orchestration ----------------
extern "C" void kernel_launch(void* const* d_in, const int* in_sizes, int n_in,
                              void* d_out, int out_size) {
    const int*   ctx   = (const int*)  d_in[0];
    const float* table = (const float*)d_in[1];
    const float* pos   = (const float*)d_in[2];
    const float* Wq    = (const float*)d_in[3];
    const float* Wk    = (const float*)d_in[4];
    const float* Wv    = (const float*)d_in[5];
    const float* Wo    = (const float*)d_in[6];
    const float* W1    = (const float*)d_in[7];
    const float* b1    = (const float*)d_in[8];
    const float* W2    = (const float*)d_in[9];
    const float* b2    = (const float*)d_in[10];

    float *z, *tmp, *an, *qkv, *o, *ff, *wt;
    cudaGetSymbolAddress((void**)&z,   g_z);
    cudaGetSymbolAddress((void**)&tmp, g_tmp);
    cudaGetSymbolAddress((void**)&an,  g_an);
    cudaGetSymbolAddress((void**)&qkv, g_qkv);
    cudaGetSymbolAddress((void**)&o,   g_o);
    cudaGetSymbolAddress((void**)&ff,  g_ff);
    cudaGetSymbolAddress((void**)&wt,  g_wt);

    embed_kernel<<<NTOK, 256>>>(ctx, table, pos);
    wt_kernel<<<dim3(EDIM, NL), 256>>>(Wq, Wk, Wv);

    const size_t wo_stride = (size_t)NH * HD * EDIM;   // 524288
    const size_t w1_stride = (size_t)EDIM * 2 * EDIM;
    const size_t w2_stride = (size_t)2 * EDIM * EDIM;

    for (int l = 0; l < NL; l++) {
        const float* wtl = wt + (size_t)l * EDIM * 1536;
        const float* wo  = Wo + (size_t)l * wo_stride;
        const float* w1  = W1 + (size_t)l * w1_stride;
        const float* bb1 = b1 + (size_t)l * 2 * EDIM;
        const float* w2  = W2 + (size_t)l * w2_stride;
        const float* bb2 = b2 + (size_t)l * EDIM;

        // qkv = z @ Wt   [4096 x 1536]
        gemm_kernel<0><<<dim3(1536 / 128, NTOK / 128), 256>>>(
            z, wtl, nullptr, nullptr, qkv, NTOK, 1536, EDIM, EDIM, 1536, 1536);

        attn_kernel<<<dim3(NTOK / 128, NH), 128>>>();

        // tmp = z + o @ Wo
        gemm_kernel<3><<<dim3(EDIM / 128, NTOK / 128), 256>>>(
            o, wo, nullptr, z, tmp, NTOK, EDIM, NH * HD, NH * HD, EDIM, EDIM);
        ln_kernel<<<NTOK, 256>>>(tmp, an);

        // ff = leaky(an @ W1 + b1)
        gemm_kernel<1><<<dim3(2 * EDIM / 128, NTOK / 128), 256>>>(
            an, w1, bb1, nullptr, ff, NTOK, 2 * EDIM, EDIM, EDIM, 2 * EDIM, 2 * EDIM);

        // tmp = an + ff @ W2 + b2
        gemm_kernel<2><<<dim3(EDIM / 128, NTOK / 128), 256>>>(
            ff, w2, bb2, an, tmp, NTOK, EDIM, 2 * EDIM, 2 * EDIM, EDIM, EDIM);
        ln_kernel<<<NTOK, 256>>>(tmp, (l == NL - 1) ? (float*)d_out : z);
    }
}